// round 1
// baseline (speedup 1.0000x reference)
#include <cuda_runtime.h>
#include <cstdint>

#define RCUT 5.2f
#define NMAX 256
#define WARPS_PER_BLK 8

// 2^y for y in [-124, 0], ~2e-6 rel error. No MUFU.
__device__ __forceinline__ float fast_exp2_neg(float y) {
    y = fmaxf(y, -124.0f);
    float nf = rintf(y);
    float f  = y - nf;            // f in [-0.5, 0.5]
    float p  = 1.3333558e-3f;
    p = fmaf(p, f, 9.6181291e-3f);
    p = fmaf(p, f, 5.5504109e-2f);
    p = fmaf(p, f, 2.4022651e-1f);
    p = fmaf(p, f, 6.9314718e-1f);
    p = fmaf(p, f, 1.0f);
    int n = (int)nf;
    return __int_as_float(__float_as_int(p) + (n << 23));
}

__global__ __launch_bounds__(32 * WARPS_PER_BLK, 8)
void radial_aev_kernel(const float* __restrict__ dmat,
                       const int*   __restrict__ species,
                       float*       __restrict__ out,
                       int N, int rows)
{
    __shared__ float shd[WARPS_PER_BLK][NMAX];
    __shared__ int   shs[WARPS_PER_BLK][NMAX];

    const int warp = threadIdx.x >> 5;
    const int lane = threadIdx.x & 31;
    const int row  = blockIdx.x * WARPS_PER_BLK + warp;
    if (row >= rows) return;

    const float* __restrict__ drow = dmat + (size_t)row * N;
    const int*   __restrict__ srow = species + (size_t)(row / N) * N;

    // ---- Phase 1: warp-ballot compaction of valid neighbors ----
    int cnt = 0;
    for (int base = 0; base < N; base += 32) {
        int j   = base + lane;
        float d = drow[j];
        bool v  = (d != 0.0f) && (d < RCUT);
        unsigned m = __ballot_sync(0xffffffffu, v);
        int pos = cnt + __popc(m & ((1u << lane) - 1u));
        if (v) {
            shd[warp][pos] = d;
            shs[warp][pos] = srow[j] - 1;   // species 1..4 -> 0..3
        }
        cnt += __popc(m);
    }
    __syncwarp();

    // ---- Phase 2: lanes 0-15 -> p for j(kk), lanes 16-31 -> p for j(kk+1) ----
    const float shf  = fmaf((float)(lane & 15), 0.26875f, 0.9f);
    const int   half = lane >> 4;

    float acc0 = 0.f, acc1 = 0.f, acc2 = 0.f, acc3 = 0.f;

    #pragma unroll 4
    for (int kk = 0; kk < cnt; kk += 2) {
        int  js  = kk + half;
        bool act = (js < cnt);
        int  jc  = act ? js : kk;

        float d  = shd[warp][jc];
        int   sp = shs[warp][jc];

        // cutoff fn: fc = 0.5 - 0.5*sin(pi*(d/RC - 0.5)), d in (0, RC)
        float v  = fmaf(d, 0.19230769230769232f, -0.5f);  // d/5.2 - 0.5
        float z  = v * v;
        float sg = fmaf(0.08214588661f, z, -0.59926452932f);
        sg = fmaf(sg, z,  2.55016403988f);
        sg = fmaf(sg, z, -5.16771278005f);
        sg = fmaf(sg, z,  3.14159265359f);
        float fc = fmaf(-0.5f, v * sg, 0.5f);

        // gaussian: exp(-16 t^2) = 2^(-23.0831207 t^2)
        float t = d - shf;
        float y = (t * t) * -23.083120654223414f;
        float e = fast_exp2_neg(y);

        float w = act ? e * fc : 0.0f;

        acc0 += (sp == 0) ? w : 0.0f;
        acc1 += (sp == 1) ? w : 0.0f;
        acc2 += (sp == 2) ? w : 0.0f;
        acc3 += (sp == 3) ? w : 0.0f;
    }

    // ---- Phase 3: combine the two j-halves, write 64 outputs ----
    acc0 += __shfl_xor_sync(0xffffffffu, acc0, 16);
    acc1 += __shfl_xor_sync(0xffffffffu, acc1, 16);
    acc2 += __shfl_xor_sync(0xffffffffu, acc2, 16);
    acc3 += __shfl_xor_sync(0xffffffffu, acc3, 16);

    if (lane < 16) {
        float* orow = out + (size_t)row * 64;
        orow[ 0 + lane] = acc0;
        orow[16 + lane] = acc1;
        orow[32 + lane] = acc2;
        orow[48 + lane] = acc3;
    }
}

extern "C" void kernel_launch(void* const* d_in, const int* in_sizes, int n_in,
                              void* d_out, int out_size)
{
    const float* dmat    = (const float*)d_in[0];
    const int*   species = (const int*)d_in[1];
    float*       out     = (float*)d_out;

    const int rows = in_sizes[1];              // B*N
    const int N    = in_sizes[0] / in_sizes[1];// N

    int grid = (rows + WARPS_PER_BLK - 1) / WARPS_PER_BLK;
    radial_aev_kernel<<<grid, 32 * WARPS_PER_BLK>>>(dmat, species, out, N, rows);
}

// round 4
// speedup vs baseline: 1.2667x; 1.2667x over previous
#include <cuda_runtime.h>
#include <cstdint>

#define RCUT 5.2f
#define WARPS_PER_BLK 8
#define SEG_CAP 264          // 256 valid + up to 4 pads, padded for alignment

__device__ __forceinline__ float ex2_approx(float x) {
    float r; asm("ex2.approx.f32 %0, %1;" : "=f"(r) : "f"(x)); return r;
}
__device__ __forceinline__ float cos_approx(float x) {
    float r; asm("cos.approx.f32 %0, %1;" : "=f"(r) : "f"(x)); return r;
}
__device__ __forceinline__ int warp_incl_scan(int v, int lane) {
    #pragma unroll
    for (int o = 1; o < 32; o <<= 1) {
        int n = __shfl_up_sync(0xffffffffu, v, o);
        if (lane >= o) v += n;
    }
    return v;
}

// Sum one species segment. Segment length is even (padded with fc=0 entries),
// lanes 0-15 handle p for element kk, lanes 16-31 handle p for element kk+1.
__device__ __forceinline__ float seg_accum(const float2* __restrict__ s,
                                           int beg, int end, int half,
                                           float A, float C) {
    float acc = 0.0f;
    #pragma unroll 2
    for (int kk = beg; kk < end; kk += 2) {
        float2 df = s[kk + half];                       // {d, fc}
        float y = fmaf(fmaf(-23.083120654223414f, df.x, A), df.x, C);
        acc = fmaf(ex2_approx(y), df.y, acc);           // exp(-eta(d-shf)^2)*fc
    }
    return acc;
}

__global__ __launch_bounds__(32 * WARPS_PER_BLK, 8)
void radial_aev_kernel(const float* __restrict__ dmat,
                       const int*   __restrict__ species,
                       float*       __restrict__ out,
                       int N, int rows)
{
    __shared__ float2 sh[WARPS_PER_BLK][SEG_CAP];

    const int warp = threadIdx.x >> 5;
    const int lane = threadIdx.x & 31;
    const int row  = blockIdx.x * WARPS_PER_BLK + warp;
    if (row >= rows) return;

    const float* __restrict__ drow = dmat + (size_t)row * N;
    const int*   __restrict__ srow = species + (size_t)(row / N) * N;

    // ---- Phase 1: per-lane-chunk load (lane owns j = 8*lane .. 8*lane+7) ----
    float dv[8]; int spv[8];
    const int j0 = lane * 8;
    if (N == 256) {
        float4 a = *(const float4*)(drow + j0);
        float4 b = *(const float4*)(drow + j0 + 4);
        int4  sa = *(const int4*)(srow + j0);
        int4  sb = *(const int4*)(srow + j0 + 4);
        dv[0]=a.x; dv[1]=a.y; dv[2]=a.z; dv[3]=a.w;
        dv[4]=b.x; dv[5]=b.y; dv[6]=b.z; dv[7]=b.w;
        spv[0]=sa.x-1; spv[1]=sa.y-1; spv[2]=sa.z-1; spv[3]=sa.w-1;
        spv[4]=sb.x-1; spv[5]=sb.y-1; spv[6]=sb.z-1; spv[7]=sb.w-1;
    } else {
        #pragma unroll
        for (int e = 0; e < 8; e++) {
            int j = j0 + e;
            dv[e]  = (j < N) ? drow[j] : 0.0f;
            spv[e] = (j < N) ? (srow[j] - 1) : 0;
        }
    }

    bool vv[8];
    int c0 = 0, c1 = 0, c2 = 0, c3 = 0;
    #pragma unroll
    for (int e = 0; e < 8; e++) {
        bool v = (dv[e] != 0.0f) && (dv[e] < RCUT);
        vv[e] = v;
        c0 += (v && spv[e] == 0);
        c1 += (v && spv[e] == 1);
        c2 += (v && spv[e] == 2);
        c3 += (v && spv[e] == 3);
    }

    // exclusive per-species offsets via warp scans, segment bases padded to even
    int i0 = warp_incl_scan(c0, lane), i1 = warp_incl_scan(c1, lane);
    int i2 = warp_incl_scan(c2, lane), i3 = warp_incl_scan(c3, lane);
    int T0 = __shfl_sync(0xffffffffu, i0, 31);
    int T1 = __shfl_sync(0xffffffffu, i1, 31);
    int T2 = __shfl_sync(0xffffffffu, i2, 31);
    int T3 = __shfl_sync(0xffffffffu, i3, 31);
    const int B0 = 0;
    const int B1 = B0 + ((T0 + 1) & ~1);
    const int B2 = B1 + ((T1 + 1) & ~1);
    const int B3 = B2 + ((T2 + 1) & ~1);
    int r0 = B0 + (i0 - c0), r1 = B1 + (i1 - c1);
    int r2 = B2 + (i2 - c2), r3 = B3 + (i3 - c3);

    // write {d, fc} into the species segments; fc computed here via MUFU so
    // all 32 lanes do distinct cos work (amortized out of the inner loop)
    const float PI_OVER_RC = 0.604152403831652f;   // pi / 5.2
    #pragma unroll
    for (int e = 0; e < 8; e++) {
        float d  = dv[e];
        float fc = fmaf(0.5f, cos_approx(d * PI_OVER_RC), 0.5f);
        int sp = spv[e];
        int pos = (sp == 0) ? r0 : (sp == 1) ? r1 : (sp == 2) ? r2 : r3;
        if (vv[e]) sh[warp][pos] = make_float2(d, fc);
        r0 += (vv[e] && sp == 0);
        r1 += (vv[e] && sp == 1);
        r2 += (vv[e] && sp == 2);
        r3 += (vv[e] && sp == 3);
    }
    __syncwarp();
    // pad odd-length segments with a zero-weight sentinel (fc = 0 -> w = 0)
    if (lane < 4) {
        int Ts = (lane == 0) ? T0 : (lane == 1) ? T1 : (lane == 2) ? T2 : T3;
        int Bs = (lane == 0) ? B0 : (lane == 1) ? B1 : (lane == 2) ? B2 : B3;
        if (Ts & 1) sh[warp][Bs + Ts] = make_float2(RCUT, 0.0f);
    }
    __syncwarp();

    // ---- Phase 2: per-segment accumulation, lane = (p, j-half) ----
    const float shf = fmaf((float)(lane & 15), 0.26875f, 0.9f);
    const float A   = 46.16624130844683f * shf;          // 2*eta/ln2 * shf
    const float C   = -23.083120654223414f * shf * shf;  // -eta/ln2 * shf^2
    const int   half = lane >> 4;
    const float2* __restrict__ s = sh[warp];

    float acc0 = seg_accum(s, B0, B0 + ((T0 + 1) & ~1), half, A, C);
    float acc1 = seg_accum(s, B1, B1 + ((T1 + 1) & ~1), half, A, C);
    float acc2 = seg_accum(s, B2, B2 + ((T2 + 1) & ~1), half, A, C);
    float acc3 = seg_accum(s, B3, B3 + ((T3 + 1) & ~1), half, A, C);

    // combine the two j-halves and write 64 outputs
    acc0 += __shfl_xor_sync(0xffffffffu, acc0, 16);
    acc1 += __shfl_xor_sync(0xffffffffu, acc1, 16);
    acc2 += __shfl_xor_sync(0xffffffffu, acc2, 16);
    acc3 += __shfl_xor_sync(0xffffffffu, acc3, 16);

    if (lane < 16) {
        float* orow = out + (size_t)row * 64;
        orow[ 0 + lane] = acc0;
        orow[16 + lane] = acc1;
        orow[32 + lane] = acc2;
        orow[48 + lane] = acc3;
    }
}

extern "C" void kernel_launch(void* const* d_in, const int* in_sizes, int n_in,
                              void* d_out, int out_size)
{
    const float* dmat    = (const float*)d_in[0];
    const int*   species = (const int*)d_in[1];
    float*       out     = (float*)d_out;

    const int rows = in_sizes[1];                 // B*N
    const int N    = in_sizes[0] / in_sizes[1];   // N

    int grid = (rows + WARPS_PER_BLK - 1) / WARPS_PER_BLK;
    radial_aev_kernel<<<grid, 32 * WARPS_PER_BLK>>>(dmat, species, out, N, rows);
}

// round 6
// speedup vs baseline: 1.2955x; 1.0227x over previous
#include <cuda_runtime.h>
#include <cstdint>

#define RCUT 5.2f
#define WARPS_PER_BLK 4
#define SEG_CAP 272           // 256 valid + up to 3 pads x 4 segments + margin
#define NK (-23.083120654223414f)   // -eta/ln2, eta=16

__device__ __forceinline__ float ex2_approx(float x) {
    float r; asm("ex2.approx.f32 %0, %1;" : "=f"(r) : "f"(x)); return r;
}
__device__ __forceinline__ float cos_approx(float x) {
    float r; asm("cos.approx.f32 %0, %1;" : "=f"(r) : "f"(x)); return r;
}

// Sum one species segment; length is a multiple of 4 (padded with fc=0).
// Lanes 0-15 take elements kk,kk+1; lanes 16-31 take kk+2,kk+3.
__device__ __forceinline__ float seg_accum(const float2* __restrict__ s,
                                           int beg, int len, int half2,
                                           float A, float C) {
    float accA = 0.0f, accB = 0.0f;
    for (int kk = beg; kk < beg + len; kk += 4) {
        float4 v4 = *(const float4*)(s + kk + half2);   // {d0,fc0,d1,fc1}
        float a0 = fmaf(fmaf(NK, v4.x, A), v4.x, C);
        float a1 = fmaf(fmaf(NK, v4.z, A), v4.z, C);
        accA = fmaf(ex2_approx(a0), v4.y, accA);
        accB = fmaf(ex2_approx(a1), v4.w, accB);
    }
    return accA + accB;
}

__global__ __launch_bounds__(32 * WARPS_PER_BLK, 12)
void radial_aev_kernel(const float* __restrict__ dmat,
                       const int*   __restrict__ species,
                       float*       __restrict__ out,
                       int N, int rows)
{
    __shared__ alignas(16) float2 sh[WARPS_PER_BLK][SEG_CAP];

    const int warp = threadIdx.x >> 5;
    const int lane = threadIdx.x & 31;
    const int row  = blockIdx.x * WARPS_PER_BLK + warp;
    if (row >= rows) return;

    const int brow = (N == 256) ? (row >> 8) : (row / N);
    const float* __restrict__ drow = dmat + (size_t)row * N;
    const int*   __restrict__ srow = species + (size_t)brow * N;

    // ---- Phase 1: per-lane chunk load (lane owns j = 8*lane .. 8*lane+7) ----
    float dv[8]; int spv[8];
    const int j0 = lane * 8;
    if (N == 256) {
        float4 a = *(const float4*)(drow + j0);
        float4 b = *(const float4*)(drow + j0 + 4);
        int4  sa = *(const int4*)(srow + j0);
        int4  sb = *(const int4*)(srow + j0 + 4);
        dv[0]=a.x; dv[1]=a.y; dv[2]=a.z; dv[3]=a.w;
        dv[4]=b.x; dv[5]=b.y; dv[6]=b.z; dv[7]=b.w;
        spv[0]=sa.x-1; spv[1]=sa.y-1; spv[2]=sa.z-1; spv[3]=sa.w-1;
        spv[4]=sb.x-1; spv[5]=sb.y-1; spv[6]=sb.z-1; spv[7]=sb.w-1;
    } else {
        #pragma unroll
        for (int e = 0; e < 8; e++) {
            int j = j0 + e;
            dv[e]  = (j < N) ? drow[j] : 0.0f;
            spv[e] = (j < N) ? (srow[j] - 1) : 0;
        }
    }

    // validity + packed per-species counts (16-bit fields: {c0|c1<<16}, {c2|c3<<16})
    int vv[8];
    int c01 = 0, c23 = 0;
    #pragma unroll
    for (int e = 0; e < 8; e++) {
        int v = (dv[e] != 0.0f) && (dv[e] < RCUT);
        vv[e] = v;
        int inc = (spv[e] & 1) ? 0x10000 : 1;
        if (v) { if (spv[e] < 2) c01 += inc; else c23 += inc; }
    }

    // packed inclusive warp scans (no cross-field borrow: fields monotone)
    int i01 = c01, i23 = c23;
    #pragma unroll
    for (int o = 1; o < 32; o <<= 1) {
        int n01 = __shfl_up_sync(0xffffffffu, i01, o);
        int n23 = __shfl_up_sync(0xffffffffu, i23, o);
        if (lane >= o) { i01 += n01; i23 += n23; }
    }
    const int t01 = __shfl_sync(0xffffffffu, i01, 31);
    const int t23 = __shfl_sync(0xffffffffu, i23, 31);
    const int T0 = t01 & 0xffff, T1 = t01 >> 16;
    const int T2 = t23 & 0xffff, T3 = t23 >> 16;
    const int L0 = (T0 + 3) & ~3, L1 = (T1 + 3) & ~3;
    const int L2 = (T2 + 3) & ~3, L3 = (T3 + 3) & ~3;
    const int B0 = 0, B1 = L0, B2 = L0 + L1, B3 = L0 + L1 + L2;

    const int e01 = i01 - c01, e23 = i23 - c23;   // exclusive (packed)
    int r0 = B0 + (e01 & 0xffff), r1 = B1 + (e01 >> 16);
    int r2 = B2 + (e23 & 0xffff), r3 = B3 + (e23 >> 16);

    // write {d, fc} into species segments; cos via MUFU (distinct work per lane)
    const float PI_OVER_RC = 0.604152403831652f;   // pi / 5.2
    #pragma unroll
    for (int e = 0; e < 8; e++) {
        float d  = dv[e];
        float fc = fmaf(0.5f, cos_approx(d * PI_OVER_RC), 0.5f);
        int sp = spv[e];
        int pos = (sp == 0) ? r0 : (sp == 1) ? r1 : (sp == 2) ? r2 : r3;
        if (vv[e]) sh[warp][pos] = make_float2(d, fc);
        r0 += (vv[e] & (sp == 0));
        r1 += (vv[e] & (sp == 1));
        r2 += (vv[e] & (sp == 2));
        r3 += (vv[e] & (sp == 3));
    }
    __syncwarp();
    // pad segment tails with zero-weight sentinels (fc = 0 -> contributes 0)
    if (lane < 4) {
        int Ts = (lane == 0) ? T0 : (lane == 1) ? T1 : (lane == 2) ? T2 : T3;
        int Ls = (lane == 0) ? L0 : (lane == 1) ? L1 : (lane == 2) ? L2 : L3;
        int Bs = (lane == 0) ? B0 : (lane == 1) ? B1 : (lane == 2) ? B2 : B3;
        for (int k = Ts; k < Ls; k++) sh[warp][Bs + k] = make_float2(1.0f, 0.0f);
    }
    __syncwarp();

    // ---- Phase 2: lane = (p = lane&15, pair-half = lane>>4), 2 j per lane/iter
    const float shf = fmaf((float)(lane & 15), 0.26875f, 0.9f);
    const float A   = -2.0f * NK * shf;     // 2*eta/ln2 * shf
    const float C   = NK * shf * shf;       // -eta/ln2 * shf^2
    const int   half2 = (lane >> 4) << 1;
    const float2* __restrict__ s = sh[warp];

    float acc0 = seg_accum(s, B0, L0, half2, A, C);
    float acc1 = seg_accum(s, B1, L1, half2, A, C);
    float acc2 = seg_accum(s, B2, L2, half2, A, C);
    float acc3 = seg_accum(s, B3, L3, half2, A, C);

    // combine the two pair-halves, write 64 outputs
    acc0 += __shfl_xor_sync(0xffffffffu, acc0, 16);
    acc1 += __shfl_xor_sync(0xffffffffu, acc1, 16);
    acc2 += __shfl_xor_sync(0xffffffffu, acc2, 16);
    acc3 += __shfl_xor_sync(0xffffffffu, acc3, 16);

    if (lane < 16) {
        float* orow = out + (size_t)row * 64;
        orow[ 0 + lane] = acc0;
        orow[16 + lane] = acc1;
        orow[32 + lane] = acc2;
        orow[48 + lane] = acc3;
    }
}

extern "C" void kernel_launch(void* const* d_in, const int* in_sizes, int n_in,
                              void* d_out, int out_size)
{
    const float* dmat    = (const float*)d_in[0];
    const int*   species = (const int*)d_in[1];
    float*       out     = (float*)d_out;

    const int rows = in_sizes[1];                 // B*N
    const int N    = in_sizes[0] / in_sizes[1];   // N

    int grid = (rows + WARPS_PER_BLK - 1) / WARPS_PER_BLK;
    radial_aev_kernel<<<grid, 32 * WARPS_PER_BLK>>>(dmat, species, out, N, rows);
}

// round 9
// speedup vs baseline: 1.5379x; 1.1872x over previous
#include <cuda_runtime.h>
#include <cstdint>

#define RCUT 5.2f
#define WPB 4
#define SEG_CAP 288                // 255 valid + up to 7 pads x 4 segments
#define NK (-23.083120654223414f)  // -eta/ln2, eta=16
#define PI_RC 0.604152403831652f   // pi / 5.2

__device__ __forceinline__ float ex2_approx(float x) {
    float r; asm("ex2.approx.f32 %0, %1;" : "=f"(r) : "f"(x)); return r;
}
__device__ __forceinline__ float cos_approx(float x) {
    float r; asm("cos.approx.f32 %0, %1;" : "=f"(r) : "f"(x)); return r;
}

// Sum one species segment; len is a multiple of 8 (padded with fc=0 entries).
// Lanes 0-15 take pairs {kk,kk+1},{kk+4,kk+5}; lanes 16-31 the other two pairs.
__device__ __forceinline__ float seg_accum(const float2* __restrict__ s,
                                           int len, int half2,
                                           float A, float C) {
    float accA = 0.0f, accB = 0.0f;
    const float4* __restrict__ p = (const float4*)(s + half2);
    for (int kk = 0; kk < len; kk += 8) {
        float4 a = p[kk >> 1];            // pairs kk+half2, kk+half2+1
        float4 b = p[(kk >> 1) + 2];      // pairs kk+4+half2, kk+4+half2+1
        float y0 = fmaf(fmaf(NK, a.x, A), a.x, C);
        float y1 = fmaf(fmaf(NK, a.z, A), a.z, C);
        float y2 = fmaf(fmaf(NK, b.x, A), b.x, C);
        float y3 = fmaf(fmaf(NK, b.z, A), b.z, C);
        accA = fmaf(ex2_approx(y0), a.y, accA);
        accB = fmaf(ex2_approx(y1), a.w, accB);
        accA = fmaf(ex2_approx(y2), b.y, accA);
        accB = fmaf(ex2_approx(y3), b.w, accB);
    }
    return accA + accB;
}

// Fast path: N == 256 (rows is a multiple of 256, grid exact).
__global__ __launch_bounds__(32 * WPB, 11)
void radial_aev_256(const float* __restrict__ dmat,
                    const int*   __restrict__ species,
                    float*       __restrict__ out)
{
    __shared__ alignas(16) float2 sh[WPB][SEG_CAP];
    __shared__ uint32_t ssp[64];   // packed bytes: ((species-1)<<4) per j

    const int warp = threadIdx.x >> 5;
    const int lane = threadIdx.x & 31;
    const int row  = blockIdx.x * WPB + warp;
    const int brow = (blockIdx.x * WPB) >> 8;   // same batch for whole block

    // ---- block-cooperative species preprocess (once per block) ----
    if (threadIdx.x < 64) {
        int4 sv = ((const int4*)(species + (size_t)brow * 256))[threadIdx.x];
        uint32_t w =  (uint32_t)((sv.x - 1) << 4)
                   | ((uint32_t)((sv.y - 1) << 4) << 8)
                   | ((uint32_t)((sv.z - 1) << 4) << 16)
                   | ((uint32_t)((sv.w - 1) << 4) << 24);
        ssp[threadIdx.x] = w;
    }
    __syncthreads();

    // ---- Phase 1: lane owns j = 8*lane .. 8*lane+7 ----
    const float* __restrict__ drow = dmat + (size_t)row * 256;
    float4 a = ((const float4*)drow)[lane * 2];
    float4 b = ((const float4*)drow)[lane * 2 + 1];
    float dv[8] = {a.x, a.y, a.z, a.w, b.x, b.y, b.z, b.w};

    const uint32_t u0 = ssp[lane * 2], u1 = ssp[lane * 2 + 1];
    int sp16[8];
    #pragma unroll
    for (int e = 0; e < 4; e++) sp16[e]     = (u0 >> (8 * e)) & 0xff;
    #pragma unroll
    for (int e = 0; e < 4; e++) sp16[e + 4] = (u1 >> (8 * e)) & 0xff;

    // validity (d>0 && d<RC  <=>  d*(RC-d)>0) + packed 8-bit per-species counts
    int vvi[8];
    uint32_t cpk = 0;
    #pragma unroll
    for (int e = 0; e < 8; e++) {
        int v = (dv[e] * (RCUT - dv[e]) > 0.0f) ? 1 : 0;
        vvi[e] = v;
        cpk += (uint32_t)v << (sp16[e] >> 1);   // sp8 = sp16>>1 in {0,8,16,24}
    }

    // single packed inclusive scan (fields monotone, max 255: no carry)
    uint32_t ipk = cpk;
    #pragma unroll
    for (int o = 1; o < 32; o <<= 1) {
        uint32_t n = __shfl_up_sync(0xffffffffu, ipk, o);
        if (lane >= o) ipk += n;
    }
    const uint32_t tot = __shfl_sync(0xffffffffu, ipk, 31);
    const uint32_t epk = ipk - cpk;             // exclusive, packed

    const int T0 = tot & 0xff, T1 = (tot >> 8) & 0xff;
    const int T2 = (tot >> 16) & 0xff, T3 = tot >> 24;
    const int L0 = (T0 + 7) & ~7, L1 = (T1 + 7) & ~7;
    const int L2 = (T2 + 7) & ~7, L3 = (T3 + 7) & ~7;
    const int B1 = L0, B2 = L0 + L1, B3 = L0 + L1 + L2;

    // packed 16-bit cursors with bases folded in
    uint32_t rlo = (epk & 0xff)                 | ((B1 + ((epk >> 8)  & 0xff)) << 16);
    uint32_t rhi = (B2 + ((epk >> 16) & 0xff))  | ((B3 + (epk >> 24))          << 16);

    float2* __restrict__ base = sh[warp];
    #pragma unroll
    for (int e = 0; e < 8; e++) {
        float d  = dv[e];
        float fc = fmaf(cos_approx(d * PI_RC), 0.5f, 0.5f);
        int  s16 = sp16[e];
        bool hi  = s16 >= 32;
        uint32_t rp = hi ? rhi : rlo;
        int sh16 = s16 & 16;
        int pos  = (rp >> sh16) & 0xffff;
        if (vvi[e]) base[pos] = make_float2(d, fc);
        uint32_t inc = (uint32_t)vvi[e] << sh16;
        if (hi) rhi += inc; else rlo += inc;
    }
    __syncwarp();

    // pad segment tails with zero-weight sentinels
    if (lane < 4) {
        int Ts = (lane == 0) ? T0 : (lane == 1) ? T1 : (lane == 2) ? T2 : T3;
        int Ls = (lane == 0) ? L0 : (lane == 1) ? L1 : (lane == 2) ? L2 : L3;
        int Bs = (lane == 0) ? 0  : (lane == 1) ? B1 : (lane == 2) ? B2 : B3;
        for (int k = Bs + Ts; k < Bs + Ls; k++) base[k] = make_float2(1.0f, 0.0f);
    }
    __syncwarp();

    // ---- Phase 2: lane = (p = lane&15, pair-half = lane>>4) ----
    const float shf = fmaf((float)(lane & 15), 0.26875f, 0.9f);
    const float A   = -2.0f * NK * shf;
    const float C   = NK * shf * shf;
    const int   half2 = (lane >> 4) << 1;

    float acc0 = seg_accum(base,      L0, half2, A, C);
    float acc1 = seg_accum(base + B1, L1, half2, A, C);
    float acc2 = seg_accum(base + B2, L2, half2, A, C);
    float acc3 = seg_accum(base + B3, L3, half2, A, C);

    acc0 += __shfl_xor_sync(0xffffffffu, acc0, 16);
    acc1 += __shfl_xor_sync(0xffffffffu, acc1, 16);
    acc2 += __shfl_xor_sync(0xffffffffu, acc2, 16);
    acc3 += __shfl_xor_sync(0xffffffffu, acc3, 16);

    if (lane < 16) {
        float* orow = out + (size_t)row * 64;
        orow[ 0 + lane] = acc0;
        orow[16 + lane] = acc1;
        orow[32 + lane] = acc2;
        orow[48 + lane] = acc3;
    }
}

// Generic fallback (any N): one warp-pair per row, direct evaluation.
__global__ void radial_aev_generic(const float* __restrict__ dmat,
                                   const int*   __restrict__ species,
                                   float*       __restrict__ out,
                                   int N, int rows)
{
    int row = blockIdx.x;
    if (row >= rows) return;
    int t = threadIdx.x;            // 64 threads: s = t>>4, p = t&15
    int s = t >> 4, p = t & 15;
    float shf = fmaf((float)p, 0.26875f, 0.9f);
    const float* drow = dmat + (size_t)row * N;
    const int*   srow = species + (size_t)(row / N) * N;
    float acc = 0.0f;
    for (int j = 0; j < N; j++) {
        float d = drow[j];
        if (d > 0.0f && d < RCUT && (srow[j] - 1) == s) {
            float fc = 0.5f * __cosf(d * PI_RC) + 0.5f;
            float tt = d - shf;
            acc += __expf(-16.0f * tt * tt) * fc;
        }
    }
    out[(size_t)row * 64 + t] = acc;
}

extern "C" void kernel_launch(void* const* d_in, const int* in_sizes, int n_in,
                              void* d_out, int out_size)
{
    const float* dmat    = (const float*)d_in[0];
    const int*   species = (const int*)d_in[1];
    float*       out     = (float*)d_out;

    const int rows = in_sizes[1];                 // B*N
    const int N    = in_sizes[0] / in_sizes[1];   // N

    if (N == 256 && (rows & (WPB - 1)) == 0) {
        radial_aev_256<<<rows / WPB, 32 * WPB>>>(dmat, species, out);
    } else {
        radial_aev_generic<<<rows, 64>>>(dmat, species, out, N, rows);
    }
}

// round 10
// speedup vs baseline: 1.5431x; 1.0034x over previous
#include <cuda_runtime.h>
#include <cstdint>

#define RCUT 5.2f
#define WPB 2
#define SEG_CAP 288                // 255 valid + up to 7 pads x 4 segments
#define NK (-23.083120654223414f)  // -eta/ln2, eta=16
#define PI_RC 0.604152403831652f   // pi / 5.2

__device__ __forceinline__ float ex2_approx(float x) {
    float r; asm("ex2.approx.f32 %0, %1;" : "=f"(r) : "f"(x)); return r;
}
__device__ __forceinline__ float cos_approx(float x) {
    float r; asm("cos.approx.f32 %0, %1;" : "=f"(r) : "f"(x)); return r;
}

// Sum one species segment; len is a multiple of 8 (padded with fc=0 entries).
// Lanes 0-15 take pairs {kk,kk+1},{kk+4,kk+5}; lanes 16-31 the other two.
__device__ __forceinline__ float seg_accum(const float2* __restrict__ s,
                                           int len, int half2,
                                           float A, float C) {
    float accA = 0.0f, accB = 0.0f;
    const float4* __restrict__ p = (const float4*)(s + half2);
    for (int kk = 0; kk < len; kk += 8) {
        float4 a = p[kk >> 1];
        float4 b = p[(kk >> 1) + 2];
        float y0 = fmaf(fmaf(NK, a.x, A), a.x, C);
        float y1 = fmaf(fmaf(NK, a.z, A), a.z, C);
        float y2 = fmaf(fmaf(NK, b.x, A), b.x, C);
        float y3 = fmaf(fmaf(NK, b.z, A), b.z, C);
        accA = fmaf(ex2_approx(y0), a.y, accA);
        accB = fmaf(ex2_approx(y1), a.w, accB);
        accA = fmaf(ex2_approx(y2), b.y, accA);
        accB = fmaf(ex2_approx(y3), b.w, accB);
    }
    return accA + accB;
}

// Fast path: N == 256.
__global__ __launch_bounds__(32 * WPB, 28)
void radial_aev_256(const float* __restrict__ dmat,
                    const int*   __restrict__ species,
                    float*       __restrict__ out)
{
    __shared__ alignas(16) float2 sh[WPB][SEG_CAP];
    __shared__ uint32_t ssp[64];   // packed bytes: ((species-1)<<4) per j

    const int warp = threadIdx.x >> 5;
    const int lane = threadIdx.x & 31;
    const int row  = blockIdx.x * WPB + warp;
    const int brow = (blockIdx.x * WPB) >> 8;   // same batch for whole block

    // ---- block-cooperative species preprocess (64 threads = whole row) ----
    {
        int4 sv = ((const int4*)(species + (size_t)brow * 256))[threadIdx.x];
        uint32_t w =  (uint32_t)((sv.x - 1) << 4)
                   | ((uint32_t)((sv.y - 1) << 4) << 8)
                   | ((uint32_t)((sv.z - 1) << 4) << 16)
                   | ((uint32_t)((sv.w - 1) << 4) << 24);
        ssp[threadIdx.x] = w;
    }
    __syncthreads();

    // ---- Phase 1: lane owns j = 8*lane .. 8*lane+7 ----
    const float* __restrict__ drow = dmat + (size_t)row * 256;
    float4 a = ((const float4*)drow)[lane * 2];
    float4 b = ((const float4*)drow)[lane * 2 + 1];
    float dv[8] = {a.x, a.y, a.z, a.w, b.x, b.y, b.z, b.w};

    const uint32_t u0 = ssp[lane * 2], u1 = ssp[lane * 2 + 1];

    // validity (0<d<RC  <=>  d*(RC-d)>0) + packed 8-bit per-species counts
    int vvi[8];
    uint32_t cpk = 0;
    #pragma unroll
    for (int e = 0; e < 8; e++) {
        int v = (dv[e] * (RCUT - dv[e]) > 0.0f) ? 1 : 0;
        vvi[e] = v;
        uint32_t uw = (e < 4) ? u0 : u1;
        int s16 = (uw >> (8 * (e & 3))) & 0xff;    // (sp-1)<<4
        cpk += (uint32_t)v << (s16 >> 1);          // shift in {0,8,16,24}
    }

    // single packed inclusive scan (8-bit fields, counts <= 255: no carry)
    uint32_t ipk = cpk;
    #pragma unroll
    for (int o = 1; o < 32; o <<= 1) {
        uint32_t n = __shfl_up_sync(0xffffffffu, ipk, o);
        if (lane >= o) ipk += n;
    }
    const uint32_t tot = __shfl_sync(0xffffffffu, ipk, 31);
    const uint32_t epk = ipk - cpk;                // exclusive, packed

    const int T0 = tot & 0xff, T1 = (tot >> 8) & 0xff;
    const int T2 = (tot >> 16) & 0xff, T3 = tot >> 24;
    const int L0 = (T0 + 7) & ~7, L1 = (T1 + 7) & ~7;
    const int L2 = (T2 + 7) & ~7, L3 = (T3 + 7) & ~7;
    const int B1 = L0, B2 = L0 + L1, B3 = L0 + L1 + L2;

    // packed 16-bit cursors with bases folded in
    uint32_t rlo = (epk & 0xff)                | ((B1 + ((epk >> 8)  & 0xff)) << 16);
    uint32_t rhi = (B2 + ((epk >> 16) & 0xff)) | ((B3 + (epk >> 24))          << 16);

    float2* __restrict__ base = sh[warp];
    #pragma unroll
    for (int e = 0; e < 8; e++) {
        float d  = dv[e];
        float fc = fmaf(cos_approx(d * PI_RC), 0.5f, 0.5f);
        uint32_t uw = (e < 4) ? u0 : u1;
        int s16 = (uw >> (8 * (e & 3))) & 0xff;
        int hi  = s16 & 32;
        int sh16 = s16 & 16;
        uint32_t rp = hi ? rhi : rlo;
        int pos = (rp >> sh16) & 0xffff;
        if (vvi[e]) base[pos] = make_float2(d, fc);
        uint32_t inc = (uint32_t)vvi[e] << sh16;
        rlo += hi ? 0u : inc;                       // SEL, no branch
        rhi += hi ? inc : 0u;
    }
    __syncwarp();

    // pad tails: lane -> (segment = lane>>3, k = lane&7), one predicated STS
    {
        int s = lane >> 3, k = lane & 7;
        int Ts = (tot >> (8 * s)) & 0xff;
        int Bs = (s == 0) ? 0 : (s == 1) ? B1 : (s == 2) ? B2 : B3;
        int Ls = (Ts + 7) & ~7;
        if (Ts + k < Ls) base[Bs + Ts + k] = make_float2(1.0f, 0.0f);
    }
    __syncwarp();

    // ---- Phase 2: lane = (p = lane&15, pair-half = lane>>4) ----
    const float shf = fmaf((float)(lane & 15), 0.26875f, 0.9f);
    const float A   = -2.0f * NK * shf;
    const float C   = NK * shf * shf;
    const int   half2 = (lane >> 4) << 1;

    float acc0 = seg_accum(base,      L0, half2, A, C);
    float acc1 = seg_accum(base + B1, L1, half2, A, C);
    float acc2 = seg_accum(base + B2, L2, half2, A, C);
    float acc3 = seg_accum(base + B3, L3, half2, A, C);

    acc0 += __shfl_xor_sync(0xffffffffu, acc0, 16);
    acc1 += __shfl_xor_sync(0xffffffffu, acc1, 16);
    acc2 += __shfl_xor_sync(0xffffffffu, acc2, 16);
    acc3 += __shfl_xor_sync(0xffffffffu, acc3, 16);

    // all 32 lanes store: lanes 0-15 write s0/s1, lanes 16-31 write s2/s3
    {
        float* orow = out + (size_t)row * 64;
        int  l15  = lane & 15;
        bool lo16 = lane < 16;
        int  off  = lo16 ? l15 : (32 + l15);
        orow[off]      = lo16 ? acc0 : acc2;
        orow[off + 16] = lo16 ? acc1 : acc3;
    }
}

// Generic fallback (any N): one 64-thread block per row, direct evaluation.
__global__ void radial_aev_generic(const float* __restrict__ dmat,
                                   const int*   __restrict__ species,
                                   float*       __restrict__ out,
                                   int N, int rows)
{
    int row = blockIdx.x;
    if (row >= rows) return;
    int t = threadIdx.x;            // 64 threads: s = t>>4, p = t&15
    int s = t >> 4, p = t & 15;
    float shf = fmaf((float)p, 0.26875f, 0.9f);
    const float* drow = dmat + (size_t)row * N;
    const int*   srow = species + (size_t)(row / N) * N;
    float acc = 0.0f;
    for (int j = 0; j < N; j++) {
        float d = drow[j];
        if (d > 0.0f && d < RCUT && (srow[j] - 1) == s) {
            float fc = 0.5f * __cosf(d * PI_RC) + 0.5f;
            float tt = d - shf;
            acc += __expf(-16.0f * tt * tt) * fc;
        }
    }
    out[(size_t)row * 64 + t] = acc;
}

extern "C" void kernel_launch(void* const* d_in, const int* in_sizes, int n_in,
                              void* d_out, int out_size)
{
    const float* dmat    = (const float*)d_in[0];
    const int*   species = (const int*)d_in[1];
    float*       out     = (float*)d_out;

    const int rows = in_sizes[1];                 // B*N
    const int N    = in_sizes[0] / in_sizes[1];   // N

    if (N == 256 && (rows & (WPB - 1)) == 0 && (rows & 255) == 0) {
        radial_aev_256<<<rows / WPB, 32 * WPB>>>(dmat, species, out);
    } else {
        radial_aev_generic<<<rows, 64>>>(dmat, species, out, N, rows);
    }
}